// round 11
// baseline (speedup 1.0000x reference)
#include <cuda_runtime.h>
#include <cuda_fp16.h>
#include <cstdint>

#define M_TOTAL 8192
#define N_TOTAL 11008
#define K_TOTAL 4096
#define GROUPS 32
#define PACKED 2048

// GEMM tiling: CTA 128x128x64, 8 warps (2M x 4N), warp tile 64x32, 3 stages.
#define BM 128
#define BN 128
#define BK 64
#define STAGES 3
#define NK_TILES (K_TOTAL / BK)   // 64
#define TILES_N (N_TOTAL / BN)    // 86
#define TILES_M (M_TOTAL / BM)    // 64
#define NTILES (TILES_N * TILES_M) // 5504
#define GROUP_M 8

// SMEM: 128B rows (BK=64 halfs), XOR-swizzled, no padding.
#define A_BYTES (BM * 128)                 // 16384
#define B_BYTES (BN * 128)                 // 16384
#define STAGE_BYTES (A_BYTES + B_BYTES)    // 32768
#define SMEM_TOTAL (STAGES * STAGE_BYTES)  // 98304

// Prep kernel split
#define DQ_BLOCKS ((N_TOTAL * (PACKED / 4) + 255) / 256)       // 22016
#define XC_BLOCKS ((M_TOTAL * K_TOTAL / 4) / 256)              // 32768

// Scratch: dequantized W (fp16) and converted x (fp16).
__device__ __half g_W[(size_t)N_TOTAL * K_TOTAL];  // ~90 MB
__device__ __half g_X[(size_t)M_TOTAL * K_TOTAL];  // ~67 MB

__device__ __forceinline__ uint32_t smem_u32(const void* p) {
    uint32_t a;
    asm("{ .reg .u64 t; cvta.to.shared.u64 t, %1; cvt.u32.u64 %0, t; }"
        : "=r"(a) : "l"(p));
    return a;
}

__device__ __forceinline__ void cp_async16(uint32_t dst, const void* src) {
    asm volatile("cp.async.cg.shared.global [%0], [%1], 16;\n" :: "r"(dst), "l"(src));
}

__device__ __forceinline__ void ldsm_x4(uint32_t (&r)[4], uint32_t addr) {
    asm volatile("ldmatrix.sync.aligned.m8n8.x4.shared.b16 {%0,%1,%2,%3}, [%4];"
                 : "=r"(r[0]), "=r"(r[1]), "=r"(r[2]), "=r"(r[3]) : "r"(addr));
}

// ---------------------------------------------------------------------------
// Kernel 1: merged prep — int4 dequant -> fp16 W, and x fp32 -> fp16.
// ---------------------------------------------------------------------------
__global__ void prep_kernel(const int4* __restrict__ wp4,
                            const float* __restrict__ scale,
                            const float* __restrict__ zp,
                            const float* __restrict__ x) {
    const int b = blockIdx.x;
    if (b < DQ_BLOCKS) {
        int c = b * 256 + threadIdx.x;
        if (c >= N_TOTAL * (PACKED / 4)) return;
        int o = c >> 9;
        int pc = c & 511;
        int g = pc >> 4;
        float s = __ldg(scale + o * GROUPS + g);
        float z = __ldg(zp + o * GROUPS + g);
        int4 v = wp4[c];
        uint4 outv;
        __half2 h0 = __floats2half2_rn(((float)((v.x >> 4) & 15) - z) * s,
                                       ((float)(v.x & 15) - z) * s);
        __half2 h1 = __floats2half2_rn(((float)((v.y >> 4) & 15) - z) * s,
                                       ((float)(v.y & 15) - z) * s);
        __half2 h2 = __floats2half2_rn(((float)((v.z >> 4) & 15) - z) * s,
                                       ((float)(v.z & 15) - z) * s);
        __half2 h3 = __floats2half2_rn(((float)((v.w >> 4) & 15) - z) * s,
                                       ((float)(v.w & 15) - z) * s);
        outv.x = *(uint32_t*)&h0;
        outv.y = *(uint32_t*)&h1;
        outv.z = *(uint32_t*)&h2;
        outv.w = *(uint32_t*)&h3;
        reinterpret_cast<uint4*>(g_W)[c] = outv;
    } else {
        int i = (b - DQ_BLOCKS) * 256 + threadIdx.x;
        float4 f = reinterpret_cast<const float4*>(x)[i];
        __half2 h0 = __floats2half2_rn(f.x, f.y);
        __half2 h1 = __floats2half2_rn(f.z, f.w);
        uint2 o;
        o.x = *(uint32_t*)&h0;
        o.y = *(uint32_t*)&h1;
        reinterpret_cast<uint2*>(g_X)[i] = o;
    }
}

// ---------------------------------------------------------------------------
// Kernel 2: persistent GEMM  out[m][n] = sum_k X[m][k] * W[n][k] + bias[n]
// R9 inner loop (JIT fragments, per-warp ks rotation). Tile loop per CTA;
// next tile's stages 0/1 are prefetched before the epilogue so the store
// phase hides the pipeline refill.
// ---------------------------------------------------------------------------
__global__ void __launch_bounds__(256, 2)
gemm_kernel(float* __restrict__ out, const float* __restrict__ bias) {
    extern __shared__ __half smem[];
    const uint32_t sb = smem_u32(smem);

    const int tid  = threadIdx.x;
    const int lane = tid & 31;
    const int warp = tid >> 5;
    const int wm = (warp & 1) * 64;
    const int wn = (warp >> 1) * 32;
    const int G = gridDim.x;

    // Per-thread constant addressing for the loader.
    uint32_t s_off[4];
    size_t   g_off[4];
#pragma unroll
    for (int i = 0; i < 4; i++) {
        int c = tid + (i << 8);
        int row = c >> 3, seg = c & 7;
        s_off[i] = (uint32_t)(row * 128) +
                   (((uint32_t)(seg * 16)) ^ (((uint32_t)row & 7u) << 4));
        g_off[i] = (size_t)row * K_TOTAL + seg * 8;
    }

    // Per-lane ldmatrix addressing.
    const int r16 = lane & 15;
    const uint32_t hi16 = (uint32_t)((lane >> 4) * 16);
    const uint32_t xorv = ((uint32_t)(r16 & 7)) << 4;
    uint32_t a_row[4], b_row[2];
#pragma unroll
    for (int mi = 0; mi < 4; mi++)
        a_row[mi] = (uint32_t)((wm + mi * 16 + r16) * 128);
#pragma unroll
    for (int ng = 0; ng < 2; ng++)
        b_row[ng] = (uint32_t)A_BYTES + (uint32_t)((wn + ng * 16 + r16) * 128);
    const uint32_t wrot = (uint32_t)(warp & 3);

    auto tile_coords = [&](int tt, int& m0_, int& n0_) {
        const int group = tt / (TILES_N * GROUP_M);
        const int rem   = tt % (TILES_N * GROUP_M);
        m0_ = (group * GROUP_M + (rem % GROUP_M)) * BM;
        n0_ = (rem / GROUP_M) * BN;
    };

    int t = blockIdx.x;
    if (t >= NTILES) return;

    int m0, n0;
    tile_coords(t, m0, n0);
    const __half* Asrc = g_X + (size_t)m0 * K_TOTAL;
    const __half* Bsrc = g_W + (size_t)n0 * K_TOTAL;

    auto load_stage = [&](int s, int k0) {
        const uint32_t base = sb + (uint32_t)s * STAGE_BYTES;
#pragma unroll
        for (int i = 0; i < 4; i++)
            cp_async16(base + s_off[i], Asrc + g_off[i] + k0);
#pragma unroll
        for (int i = 0; i < 4; i++)
            cp_async16(base + (uint32_t)A_BYTES + s_off[i], Bsrc + g_off[i] + k0);
        asm volatile("cp.async.commit_group;\n" ::: "memory");
    };

    load_stage(0, 0);
    load_stage(1, BK);

    for (; t < NTILES; t += G) {
        float acc[4][4][4];
#pragma unroll
        for (int mi = 0; mi < 4; mi++)
#pragma unroll
            for (int ni = 0; ni < 4; ni++)
#pragma unroll
                for (int e = 0; e < 4; e++) acc[mi][ni][e] = 0.0f;

        for (int i = 0; i < NK_TILES; i++) {
            asm volatile("cp.async.wait_group 1;\n" ::: "memory");
            __syncthreads();
            // Slot (i+2)%3 (== (i-1)%3) was fully consumed before the barrier.
            if (i + 2 < NK_TILES) {
                load_stage((i + 2) % STAGES, (i + 2) * BK);
            } else {
                asm volatile("cp.async.commit_group;\n" ::: "memory");
            }

            const uint32_t st = sb + (uint32_t)((i % STAGES) * STAGE_BYTES);
#pragma unroll
            for (int j = 0; j < 4; j++) {
                const uint32_t ksb = ((j + wrot) & 3u) << 5;
                const uint32_t colb = (ksb + hi16) ^ xorv;
                uint32_t a[4][4];
#pragma unroll
                for (int mi = 0; mi < 4; mi++)
                    ldsm_x4(a[mi], st + a_row[mi] + colb);
                uint32_t b[4][2];
#pragma unroll
                for (int ng = 0; ng < 2; ng++) {
                    uint32_t r[4];
                    ldsm_x4(r, st + b_row[ng] + colb);
                    b[ng * 2 + 0][0] = r[0]; b[ng * 2 + 0][1] = r[2];
                    b[ng * 2 + 1][0] = r[1]; b[ng * 2 + 1][1] = r[3];
                }
#pragma unroll
                for (int mi = 0; mi < 4; mi++)
#pragma unroll
                    for (int ni = 0; ni < 4; ni++) {
                        asm volatile(
                            "mma.sync.aligned.m16n8k16.row.col.f32.f16.f16.f32 "
                            "{%0,%1,%2,%3}, {%4,%5,%6,%7}, {%8,%9}, {%0,%1,%2,%3};\n"
                            : "+f"(acc[mi][ni][0]), "+f"(acc[mi][ni][1]),
                              "+f"(acc[mi][ni][2]), "+f"(acc[mi][ni][3])
                            : "r"(a[mi][0]), "r"(a[mi][1]),
                              "r"(a[mi][2]), "r"(a[mi][3]),
                              "r"(b[ni][0]), "r"(b[ni][1]));
                    }
            }
        }

        // All warps done reading SMEM for this tile before boundary loads.
        __syncthreads();

        const int em0 = m0, en0 = n0;
        const int nt = t + G;
        if (nt < NTILES) {
            tile_coords(nt, m0, n0);
            Asrc = g_X + (size_t)m0 * K_TOTAL;
            Bsrc = g_W + (size_t)n0 * K_TOTAL;
            load_stage(0, 0);     // overlaps with epilogue below
            load_stage(1, BK);
        } else {
            asm volatile("cp.async.commit_group;\n" ::: "memory");
            asm volatile("cp.async.commit_group;\n" ::: "memory");
        }

        // Epilogue: bias + fp32 store (hides next tile's pipeline refill).
        const int r  = lane >> 2;
        const int c2 = (lane & 3) * 2;
#pragma unroll
        for (int mi = 0; mi < 4; mi++) {
            const int row = em0 + wm + mi * 16 + r;
            float* o0 = out + (size_t)row * N_TOTAL + en0 + wn;
            float* o1 = o0 + (size_t)8 * N_TOTAL;
#pragma unroll
            for (int ni = 0; ni < 4; ni++) {
                const int col = ni * 8 + c2;
                const float b0 = __ldg(bias + en0 + wn + col);
                const float b1 = __ldg(bias + en0 + wn + col + 1);
                *reinterpret_cast<float2*>(o0 + col) =
                    make_float2(acc[mi][ni][0] + b0, acc[mi][ni][1] + b1);
                *reinterpret_cast<float2*>(o1 + col) =
                    make_float2(acc[mi][ni][2] + b0, acc[mi][ni][3] + b1);
            }
        }
    }
}

// ---------------------------------------------------------------------------
// Launch
// ---------------------------------------------------------------------------
extern "C" void kernel_launch(void* const* d_in, const int* in_sizes, int n_in,
                              void* d_out, int out_size) {
    const float* x     = (const float*)d_in[0];
    const int*   wp    = (const int*)d_in[1];
    const float* scale = (const float*)d_in[2];
    const float* zp    = (const float*)d_in[3];
    const float* bias  = (const float*)d_in[4];
    float* out = (float*)d_out;

    prep_kernel<<<DQ_BLOCKS + XC_BLOCKS, 256>>>((const int4*)wp, scale, zp, x);

    int dev = 0, sms = 148;
    cudaGetDevice(&dev);
    cudaDeviceGetAttribute(&sms, cudaDevAttrMultiProcessorCount, dev);
    int grid = 2 * sms;               // persistent: one resident wave
    if (grid > NTILES) grid = NTILES;

    cudaFuncSetAttribute(gemm_kernel,
                         cudaFuncAttributeMaxDynamicSharedMemorySize, SMEM_TOTAL);
    gemm_kernel<<<grid, 256, SMEM_TOTAL>>>(out, bias);
}

// round 13
// speedup vs baseline: 1.0854x; 1.0854x over previous
#include <cuda_runtime.h>
#include <cuda_fp16.h>
#include <cstdint>

#define M_TOTAL 8192
#define N_TOTAL 11008
#define K_TOTAL 4096
#define GROUPS 32
#define PACKED 2048

// GEMM tiling: CTA 128x128x64, 8 warps (2M x 4N), warp tile 64x32, 3 stages.
#define BM 128
#define BN 128
#define BK 64
#define STAGES 3
#define NK_TILES (K_TOTAL / BK)   // 64
#define TILES_N (N_TOTAL / BN)    // 86
#define TILES_M (M_TOTAL / BM)    // 64
#define GROUP_M 8

// SMEM: 128B rows (BK=64 halfs), XOR-swizzled, no padding.
#define A_BYTES (BM * 128)                 // 16384
#define B_BYTES (BN * 128)                 // 16384
#define STAGE_BYTES (A_BYTES + B_BYTES)    // 32768
#define SMEM_TOTAL (STAGES * STAGE_BYTES)  // 98304

// Prep kernel split
#define DQ_BLOCKS ((N_TOTAL * (PACKED / 4) + 255) / 256)       // 22016
#define XC_BLOCKS ((M_TOTAL * K_TOTAL / 4) / 256)              // 32768

// Scratch: dequantized W (fp16) and converted x (fp16).
__device__ __half g_W[(size_t)N_TOTAL * K_TOTAL];  // ~90 MB
__device__ __half g_X[(size_t)M_TOTAL * K_TOTAL];  // ~67 MB

__device__ __forceinline__ uint32_t smem_u32(const void* p) {
    uint32_t a;
    asm("{ .reg .u64 t; cvta.to.shared.u64 t, %1; cvt.u32.u64 %0, t; }"
        : "=r"(a) : "l"(p));
    return a;
}

__device__ __forceinline__ void cp_async16(uint32_t dst, const void* src) {
    asm volatile("cp.async.cg.shared.global [%0], [%1], 16;\n" :: "r"(dst), "l"(src));
}

__device__ __forceinline__ void ldsm_x4(uint32_t (&r)[4], uint32_t addr) {
    asm volatile("ldmatrix.sync.aligned.m8n8.x4.shared.b16 {%0,%1,%2,%3}, [%4];"
                 : "=r"(r[0]), "=r"(r[1]), "=r"(r[2]), "=r"(r[3]) : "r"(addr));
}

// ---------------------------------------------------------------------------
// Kernel 1: merged prep — int4 dequant -> fp16 W, and x fp32 -> fp16.
// Streaming loads/stores: this data is write-once, read much later.
// ---------------------------------------------------------------------------
__global__ void prep_kernel(const int4* __restrict__ wp4,
                            const float* __restrict__ scale,
                            const float* __restrict__ zp,
                            const float* __restrict__ x) {
    const int b = blockIdx.x;
    if (b < DQ_BLOCKS) {
        int c = b * 256 + threadIdx.x;
        if (c >= N_TOTAL * (PACKED / 4)) return;
        int o = c >> 9;
        int pc = c & 511;
        int g = pc >> 4;
        float s = __ldg(scale + o * GROUPS + g);
        float z = __ldg(zp + o * GROUPS + g);
        int4 v = __ldcs(wp4 + c);
        uint4 outv;
        __half2 h0 = __floats2half2_rn(((float)((v.x >> 4) & 15) - z) * s,
                                       ((float)(v.x & 15) - z) * s);
        __half2 h1 = __floats2half2_rn(((float)((v.y >> 4) & 15) - z) * s,
                                       ((float)(v.y & 15) - z) * s);
        __half2 h2 = __floats2half2_rn(((float)((v.z >> 4) & 15) - z) * s,
                                       ((float)(v.z & 15) - z) * s);
        __half2 h3 = __floats2half2_rn(((float)((v.w >> 4) & 15) - z) * s,
                                       ((float)(v.w & 15) - z) * s);
        outv.x = *(uint32_t*)&h0;
        outv.y = *(uint32_t*)&h1;
        outv.z = *(uint32_t*)&h2;
        outv.w = *(uint32_t*)&h3;
        __stcs(reinterpret_cast<uint4*>(g_W) + c, outv);
    } else {
        int i = (b - DQ_BLOCKS) * 256 + threadIdx.x;
        float4 f = __ldcs(reinterpret_cast<const float4*>(x) + i);
        __half2 h0 = __floats2half2_rn(f.x, f.y);
        __half2 h1 = __floats2half2_rn(f.z, f.w);
        uint2 o;
        o.x = *(uint32_t*)&h0;
        o.y = *(uint32_t*)&h1;
        __stcs(reinterpret_cast<uint2*>(g_X) + i, o);
    }
}

// ---------------------------------------------------------------------------
// Kernel 2: GEMM  out[m][n] = sum_k X[m][k] * W[n][k] + bias[n]
// R9 structure; stage prefetch deferred until after chunk 0 to decongest the
// post-barrier issue window.
// ---------------------------------------------------------------------------
__global__ void __launch_bounds__(256, 2)
gemm_kernel(float* __restrict__ out, const float* __restrict__ bias) {
    extern __shared__ __half smem[];
    const uint32_t sb = smem_u32(smem);

    const int tid  = threadIdx.x;
    const int lane = tid & 31;
    const int warp = tid >> 5;
    const int wm = (warp & 1) * 64;
    const int wn = (warp >> 1) * 32;

    // Supertile raster: groups of GROUP_M m-tiles; within a group, m-fast.
    const int bid = blockIdx.x;
    const int group = bid / (TILES_N * GROUP_M);
    const int rem   = bid % (TILES_N * GROUP_M);
    const int m0 = (group * GROUP_M + (rem % GROUP_M)) * BM;
    const int n0 = (rem / GROUP_M) * BN;

    float acc[4][4][4];
#pragma unroll
    for (int mi = 0; mi < 4; mi++)
#pragma unroll
        for (int ni = 0; ni < 4; ni++)
#pragma unroll
            for (int e = 0; e < 4; e++) acc[mi][ni][e] = 0.0f;

    // Hoisted loader addressing.
    uint32_t s_off[4];
    const __half* a_src[4];
    const __half* b_src[4];
    {
        const __half* Ag = g_X + (size_t)m0 * K_TOTAL;
        const __half* Bg = g_W + (size_t)n0 * K_TOTAL;
#pragma unroll
        for (int i = 0; i < 4; i++) {
            int c = tid + (i << 8);
            int row = c >> 3, seg = c & 7;
            s_off[i] = (uint32_t)(row * 128) +
                       (((uint32_t)(seg * 16)) ^ (((uint32_t)row & 7u) << 4));
            a_src[i] = Ag + (size_t)row * K_TOTAL + seg * 8;
            b_src[i] = Bg + (size_t)row * K_TOTAL + seg * 8;
        }
    }

    auto load_stage = [&](int s, int k0) {
        const uint32_t base = sb + (uint32_t)s * STAGE_BYTES;
#pragma unroll
        for (int i = 0; i < 4; i++)
            cp_async16(base + s_off[i], a_src[i] + k0);
#pragma unroll
        for (int i = 0; i < 4; i++)
            cp_async16(base + (uint32_t)A_BYTES + s_off[i], b_src[i] + k0);
        asm volatile("cp.async.commit_group;\n" ::: "memory");
    };

    load_stage(0, 0);
    load_stage(1, BK);

    // Per-lane ldmatrix addressing.
    const int r16 = lane & 15;
    const uint32_t hi16 = (uint32_t)((lane >> 4) * 16);
    const uint32_t xorv = ((uint32_t)(r16 & 7)) << 4;
    uint32_t a_row[4], b_row[2];
#pragma unroll
    for (int mi = 0; mi < 4; mi++)
        a_row[mi] = (uint32_t)((wm + mi * 16 + r16) * 128);
#pragma unroll
    for (int ng = 0; ng < 2; ng++)
        b_row[ng] = (uint32_t)A_BYTES + (uint32_t)((wn + ng * 16 + r16) * 128);

    const uint32_t wrot = (uint32_t)(warp & 3);

    // One chunk of LDSM + MMA.
    auto do_chunk = [&](uint32_t st, int j) {
        const uint32_t ksb = (((uint32_t)j + wrot) & 3u) << 5;   // ks*2 bytes
        const uint32_t colb = (ksb + hi16) ^ xorv;
        uint32_t a[4][4];
#pragma unroll
        for (int mi = 0; mi < 4; mi++)
            ldsm_x4(a[mi], st + a_row[mi] + colb);
        uint32_t b[4][2];
#pragma unroll
        for (int ng = 0; ng < 2; ng++) {
            uint32_t r[4];
            ldsm_x4(r, st + b_row[ng] + colb);
            b[ng * 2 + 0][0] = r[0]; b[ng * 2 + 0][1] = r[2];
            b[ng * 2 + 1][0] = r[1]; b[ng * 2 + 1][1] = r[3];
        }
#pragma unroll
        for (int mi = 0; mi < 4; mi++)
#pragma unroll
            for (int ni = 0; ni < 4; ni++) {
                asm volatile(
                    "mma.sync.aligned.m16n8k16.row.col.f32.f16.f16.f32 "
                    "{%0,%1,%2,%3}, {%4,%5,%6,%7}, {%8,%9}, {%0,%1,%2,%3};\n"
                    : "+f"(acc[mi][ni][0]), "+f"(acc[mi][ni][1]),
                      "+f"(acc[mi][ni][2]), "+f"(acc[mi][ni][3])
                    : "r"(a[mi][0]), "r"(a[mi][1]), "r"(a[mi][2]), "r"(a[mi][3]),
                      "r"(b[ni][0]), "r"(b[ni][1]));
            }
    };

    for (int i = 0; i < NK_TILES; i++) {
        asm volatile("cp.async.wait_group 1;\n" ::: "memory");
        __syncthreads();

        const uint32_t st = sb + (uint32_t)((i % STAGES) * STAGE_BYTES);

        // Chunk 0 first: get fragment loads in flight in the post-barrier
        // window, then issue the next-stage cp.async (slot (i+2)%3 was fully
        // consumed before the barrier; cp.async ordering is in-order so the
        // wait_group accounting is unchanged).
        do_chunk(st, 0);

        if (i + 2 < NK_TILES) {
            load_stage((i + 2) % STAGES, (i + 2) * BK);
        } else {
            asm volatile("cp.async.commit_group;\n" ::: "memory");
        }

#pragma unroll
        for (int j = 1; j < 4; j++) do_chunk(st, j);
    }

    // Epilogue: bias + fp32 store.
    const int r  = lane >> 2;
    const int c2 = (lane & 3) * 2;
#pragma unroll
    for (int mi = 0; mi < 4; mi++) {
        const int row = m0 + wm + mi * 16 + r;
        float* o0 = out + (size_t)row * N_TOTAL + n0 + wn;
        float* o1 = o0 + (size_t)8 * N_TOTAL;
#pragma unroll
        for (int ni = 0; ni < 4; ni++) {
            const int col = ni * 8 + c2;
            const float b0 = __ldg(bias + n0 + wn + col);
            const float b1 = __ldg(bias + n0 + wn + col + 1);
            *reinterpret_cast<float2*>(o0 + col) =
                make_float2(acc[mi][ni][0] + b0, acc[mi][ni][1] + b1);
            *reinterpret_cast<float2*>(o1 + col) =
                make_float2(acc[mi][ni][2] + b0, acc[mi][ni][3] + b1);
        }
    }
}

// ---------------------------------------------------------------------------
// Launch
// ---------------------------------------------------------------------------
extern "C" void kernel_launch(void* const* d_in, const int* in_sizes, int n_in,
                              void* d_out, int out_size) {
    const float* x     = (const float*)d_in[0];
    const int*   wp    = (const int*)d_in[1];
    const float* scale = (const float*)d_in[2];
    const float* zp    = (const float*)d_in[3];
    const float* bias  = (const float*)d_in[4];
    float* out = (float*)d_out;

    prep_kernel<<<DQ_BLOCKS + XC_BLOCKS, 256>>>((const int4*)wp, scale, zp, x);

    cudaFuncSetAttribute(gemm_kernel,
                         cudaFuncAttributeMaxDynamicSharedMemorySize, SMEM_TOTAL);
    gemm_kernel<<<TILES_N * TILES_M, 256, SMEM_TOTAL>>>(out, bias);
}

// round 14
// speedup vs baseline: 1.0895x; 1.0037x over previous
#include <cuda_runtime.h>
#include <cuda_fp16.h>
#include <cstdint>

#define M_TOTAL 8192
#define N_TOTAL 11008
#define K_TOTAL 4096
#define GROUPS 32
#define PACKED 2048

// GEMM tiling: CTA 128x128x64, 8 warps (2M x 4N), warp tile 64x32, 3 stages.
#define BM 128
#define BN 128
#define BK 64
#define STAGES 3
#define NK_TILES (K_TOTAL / BK)   // 64
#define TILES_N (N_TOTAL / BN)    // 86
#define TILES_M (M_TOTAL / BM)    // 64
#define GROUP_M 8

// SMEM: 128B rows (BK=64 halfs), XOR-swizzled, no padding.
#define A_BYTES (BM * 128)                 // 16384
#define B_BYTES (BN * 128)                 // 16384
#define STAGE_BYTES (A_BYTES + B_BYTES)    // 32768
#define SMEM_TOTAL (STAGES * STAGE_BYTES)  // 98304

// Prep kernel split
#define DQ_BLOCKS ((N_TOTAL * (PACKED / 4) + 255) / 256)       // 22016
#define XC_BLOCKS ((M_TOTAL * K_TOTAL / 4) / 256)              // 32768

// Scratch: dequantized W (fp16) and converted x (fp16).
__device__ __half g_W[(size_t)N_TOTAL * K_TOTAL];  // ~90 MB
__device__ __half g_X[(size_t)M_TOTAL * K_TOTAL];  // ~67 MB

__device__ __forceinline__ uint32_t smem_u32(const void* p) {
    uint32_t a;
    asm("{ .reg .u64 t; cvta.to.shared.u64 t, %1; cvt.u32.u64 %0, t; }"
        : "=r"(a) : "l"(p));
    return a;
}

__device__ __forceinline__ void cp_async16(uint32_t dst, const void* src) {
    asm volatile("cp.async.cg.shared.global [%0], [%1], 16;\n" :: "r"(dst), "l"(src));
}

__device__ __forceinline__ void ldsm_x4(uint32_t (&r)[4], uint32_t addr) {
    asm volatile("ldmatrix.sync.aligned.m8n8.x4.shared.b16 {%0,%1,%2,%3}, [%4];"
                 : "=r"(r[0]), "=r"(r[1]), "=r"(r[2]), "=r"(r[3]) : "r"(addr));
}

// ---------------------------------------------------------------------------
// Kernel 1: merged prep — int4 dequant -> fp16 W, and x fp32 -> fp16.
// Streaming loads/stores: this data is write-once, read much later.
// ---------------------------------------------------------------------------
__global__ void prep_kernel(const int4* __restrict__ wp4,
                            const float* __restrict__ scale,
                            const float* __restrict__ zp,
                            const float* __restrict__ x) {
    const int b = blockIdx.x;
    if (b < DQ_BLOCKS) {
        int c = b * 256 + threadIdx.x;
        if (c >= N_TOTAL * (PACKED / 4)) return;
        int o = c >> 9;
        int pc = c & 511;
        int g = pc >> 4;
        float s = __ldg(scale + o * GROUPS + g);
        float z = __ldg(zp + o * GROUPS + g);
        int4 v = __ldcs(wp4 + c);
        uint4 outv;
        __half2 h0 = __floats2half2_rn(((float)((v.x >> 4) & 15) - z) * s,
                                       ((float)(v.x & 15) - z) * s);
        __half2 h1 = __floats2half2_rn(((float)((v.y >> 4) & 15) - z) * s,
                                       ((float)(v.y & 15) - z) * s);
        __half2 h2 = __floats2half2_rn(((float)((v.z >> 4) & 15) - z) * s,
                                       ((float)(v.z & 15) - z) * s);
        __half2 h3 = __floats2half2_rn(((float)((v.w >> 4) & 15) - z) * s,
                                       ((float)(v.w & 15) - z) * s);
        outv.x = *(uint32_t*)&h0;
        outv.y = *(uint32_t*)&h1;
        outv.z = *(uint32_t*)&h2;
        outv.w = *(uint32_t*)&h3;
        __stcs(reinterpret_cast<uint4*>(g_W) + c, outv);
    } else {
        int i = (b - DQ_BLOCKS) * 256 + threadIdx.x;
        float4 f = __ldcs(reinterpret_cast<const float4*>(x) + i);
        __half2 h0 = __floats2half2_rn(f.x, f.y);
        __half2 h1 = __floats2half2_rn(f.z, f.w);
        uint2 o;
        o.x = *(uint32_t*)&h0;
        o.y = *(uint32_t*)&h1;
        __stcs(reinterpret_cast<uint2*>(g_X) + i, o);
    }
}

// ---------------------------------------------------------------------------
// Kernel 2: GEMM  out[m][n] = sum_k X[m][k] * W[n][k] + bias[n]
// R13 structure + hoisted colb, hoisted bias, streaming output stores.
// ---------------------------------------------------------------------------
__global__ void __launch_bounds__(256, 2)
gemm_kernel(float* __restrict__ out, const float* __restrict__ bias) {
    extern __shared__ __half smem[];
    const uint32_t sb = smem_u32(smem);

    const int tid  = threadIdx.x;
    const int lane = tid & 31;
    const int warp = tid >> 5;
    const int wm = (warp & 1) * 64;
    const int wn = (warp >> 1) * 32;

    // Supertile raster: groups of GROUP_M m-tiles; within a group, m-fast.
    const int bid = blockIdx.x;
    const int group = bid / (TILES_N * GROUP_M);
    const int rem   = bid % (TILES_N * GROUP_M);
    const int m0 = (group * GROUP_M + (rem % GROUP_M)) * BM;
    const int n0 = (rem / GROUP_M) * BN;

    float acc[4][4][4];
#pragma unroll
    for (int mi = 0; mi < 4; mi++)
#pragma unroll
        for (int ni = 0; ni < 4; ni++)
#pragma unroll
            for (int e = 0; e < 4; e++) acc[mi][ni][e] = 0.0f;

    // Hoisted loader addressing.
    uint32_t s_off[4];
    const __half* a_src[4];
    const __half* b_src[4];
    {
        const __half* Ag = g_X + (size_t)m0 * K_TOTAL;
        const __half* Bg = g_W + (size_t)n0 * K_TOTAL;
#pragma unroll
        for (int i = 0; i < 4; i++) {
            int c = tid + (i << 8);
            int row = c >> 3, seg = c & 7;
            s_off[i] = (uint32_t)(row * 128) +
                       (((uint32_t)(seg * 16)) ^ (((uint32_t)row & 7u) << 4));
            a_src[i] = Ag + (size_t)row * K_TOTAL + seg * 8;
            b_src[i] = Bg + (size_t)row * K_TOTAL + seg * 8;
        }
    }

    auto load_stage = [&](int s, int k0) {
        const uint32_t base = sb + (uint32_t)s * STAGE_BYTES;
#pragma unroll
        for (int i = 0; i < 4; i++)
            cp_async16(base + s_off[i], a_src[i] + k0);
#pragma unroll
        for (int i = 0; i < 4; i++)
            cp_async16(base + (uint32_t)A_BYTES + s_off[i], b_src[i] + k0);
        asm volatile("cp.async.commit_group;\n" ::: "memory");
    };

    load_stage(0, 0);
    load_stage(1, BK);

    // Per-lane ldmatrix addressing (all loop-invariant; colb hoisted per chunk).
    const int r16 = lane & 15;
    const uint32_t hi16 = (uint32_t)((lane >> 4) * 16);
    const uint32_t xorv = ((uint32_t)(r16 & 7)) << 4;
    const uint32_t wrot = (uint32_t)(warp & 3);
    uint32_t a_row[4], b_row[2], colb[4];
#pragma unroll
    for (int mi = 0; mi < 4; mi++)
        a_row[mi] = (uint32_t)((wm + mi * 16 + r16) * 128);
#pragma unroll
    for (int ng = 0; ng < 2; ng++)
        b_row[ng] = (uint32_t)A_BYTES + (uint32_t)((wn + ng * 16 + r16) * 128);
#pragma unroll
    for (int j = 0; j < 4; j++)
        colb[j] = (((((uint32_t)j + wrot) & 3u) << 5) + hi16) ^ xorv;

    // One chunk of LDSM + MMA.
    auto do_chunk = [&](uint32_t st, int j) {
        const uint32_t cb = colb[j];
        uint32_t a[4][4];
#pragma unroll
        for (int mi = 0; mi < 4; mi++)
            ldsm_x4(a[mi], st + a_row[mi] + cb);
        uint32_t b[4][2];
#pragma unroll
        for (int ng = 0; ng < 2; ng++) {
            uint32_t r[4];
            ldsm_x4(r, st + b_row[ng] + cb);
            b[ng * 2 + 0][0] = r[0]; b[ng * 2 + 0][1] = r[2];
            b[ng * 2 + 1][0] = r[1]; b[ng * 2 + 1][1] = r[3];
        }
#pragma unroll
        for (int mi = 0; mi < 4; mi++)
#pragma unroll
            for (int ni = 0; ni < 4; ni++) {
                asm volatile(
                    "mma.sync.aligned.m16n8k16.row.col.f32.f16.f16.f32 "
                    "{%0,%1,%2,%3}, {%4,%5,%6,%7}, {%8,%9}, {%0,%1,%2,%3};\n"
                    : "+f"(acc[mi][ni][0]), "+f"(acc[mi][ni][1]),
                      "+f"(acc[mi][ni][2]), "+f"(acc[mi][ni][3])
                    : "r"(a[mi][0]), "r"(a[mi][1]), "r"(a[mi][2]), "r"(a[mi][3]),
                      "r"(b[ni][0]), "r"(b[ni][1]));
            }
    };

    for (int i = 0; i < NK_TILES; i++) {
        asm volatile("cp.async.wait_group 1;\n" ::: "memory");
        __syncthreads();

        const uint32_t st = sb + (uint32_t)((i % STAGES) * STAGE_BYTES);

        // Chunk 0 first (fragment loads in flight), then next-stage prefetch.
        do_chunk(st, 0);

        if (i + 2 < NK_TILES) {
            load_stage((i + 2) % STAGES, (i + 2) * BK);
        } else {
            asm volatile("cp.async.commit_group;\n" ::: "memory");
        }

#pragma unroll
        for (int j = 1; j < 4; j++) do_chunk(st, j);
    }

    // Epilogue: bias (hoisted) + streaming fp32 stores.
    const int r  = lane >> 2;
    const int c2 = (lane & 3) * 2;
    float bc0[4], bc1[4];
#pragma unroll
    for (int ni = 0; ni < 4; ni++) {
        bc0[ni] = __ldg(bias + n0 + wn + ni * 8 + c2);
        bc1[ni] = __ldg(bias + n0 + wn + ni * 8 + c2 + 1);
    }
#pragma unroll
    for (int mi = 0; mi < 4; mi++) {
        const int row = m0 + wm + mi * 16 + r;
        float* o0 = out + (size_t)row * N_TOTAL + n0 + wn;
        float* o1 = o0 + (size_t)8 * N_TOTAL;
#pragma unroll
        for (int ni = 0; ni < 4; ni++) {
            const int col = ni * 8 + c2;
            __stcs(reinterpret_cast<float2*>(o0 + col),
                   make_float2(acc[mi][ni][0] + bc0[ni], acc[mi][ni][1] + bc1[ni]));
            __stcs(reinterpret_cast<float2*>(o1 + col),
                   make_float2(acc[mi][ni][2] + bc0[ni], acc[mi][ni][3] + bc1[ni]));
        }
    }
}

// ---------------------------------------------------------------------------
// Launch
// ---------------------------------------------------------------------------
extern "C" void kernel_launch(void* const* d_in, const int* in_sizes, int n_in,
                              void* d_out, int out_size) {
    const float* x     = (const float*)d_in[0];
    const int*   wp    = (const int*)d_in[1];
    const float* scale = (const float*)d_in[2];
    const float* zp    = (const float*)d_in[3];
    const float* bias  = (const float*)d_in[4];
    float* out = (float*)d_out;

    prep_kernel<<<DQ_BLOCKS + XC_BLOCKS, 256>>>((const int4*)wp, scale, zp, x);

    cudaFuncSetAttribute(gemm_kernel,
                         cudaFuncAttributeMaxDynamicSharedMemorySize, SMEM_TOTAL);
    gemm_kernel<<<TILES_N * TILES_M, 256, SMEM_TOTAL>>>(out, bias);
}